// round 1
// baseline (speedup 1.0000x reference)
#include <cuda_runtime.h>
#include <math.h>

// Problem constants
#define TT 4096   // tokens (B*S)
#define DD 2048   // hidden
#define II 1024   // intermediate
#define EE 8      // experts
#define RTOT (2*TT)  // total routed rows (top-2, always exactly 8192)

// ---------------- scratch (device globals; allocation-free rule) ----------------
__device__ float g_sg[(size_t)TT * II];        // shared gate = x @ Wg        (16.7 MB)
__device__ float g_sh[(size_t)TT * II];        // shared h = silu(g)*u        (16.7 MB)
__device__ float g_gu[(size_t)RTOT * 2 * II];  // routed gate_up out          (67 MB)
__device__ float g_rh[(size_t)RTOT * II];      // routed h                    (33.5 MB)
__device__ int   g_e0[TT];
__device__ int   g_e1[TT];
__device__ float g_p0[TT];
__device__ float g_p1[TT];
__device__ int   g_cnt[EE];
__device__ int   g_off[EE];
__device__ int   g_ltok[EE * TT];
__device__ float g_lp[EE * TT];

__device__ __forceinline__ float siluf(float v) {
    return v / (1.0f + __expf(-v));
}

// ---------------- router: logits = x @ router_w, top-2, sigmoid ----------------
__global__ void router_kernel(const float* __restrict__ x, const float* __restrict__ rw) {
    int gwarp = (blockIdx.x * blockDim.x + threadIdx.x) >> 5;
    int lane = threadIdx.x & 31;
    if (gwarp >= TT) return;
    const float* xr = x + (size_t)gwarp * DD;
    float acc[8] = {0.f,0.f,0.f,0.f,0.f,0.f,0.f,0.f};
    for (int d = lane; d < DD; d += 32) {
        float xv = xr[d];
        const float4* r4 = (const float4*)(rw + (size_t)d * EE);
        float4 a = r4[0], b = r4[1];
        acc[0] += xv * a.x; acc[1] += xv * a.y; acc[2] += xv * a.z; acc[3] += xv * a.w;
        acc[4] += xv * b.x; acc[5] += xv * b.y; acc[6] += xv * b.z; acc[7] += xv * b.w;
    }
    #pragma unroll
    for (int e = 0; e < 8; e++) {
        #pragma unroll
        for (int s = 16; s > 0; s >>= 1)
            acc[e] += __shfl_xor_sync(0xffffffffu, acc[e], s);
    }
    if (lane == 0) {
        int i0 = 0; float v0 = acc[0];
        #pragma unroll
        for (int e = 1; e < 8; e++) if (acc[e] > v0) { v0 = acc[e]; i0 = e; }
        int i1 = -1; float v1 = -3.4e38f;
        #pragma unroll
        for (int e = 0; e < 8; e++) if (e != i0 && acc[e] > v1) { v1 = acc[e]; i1 = e; }
        g_e0[gwarp] = i0; g_e1[gwarp] = i1;
        g_p0[gwarp] = 1.0f / (1.0f + __expf(-v0));
        g_p1[gwarp] = 1.0f / (1.0f + __expf(-v1));
    }
}

// ---------------- deterministic per-expert token compaction ----------------
__global__ void build_lists_kernel() {
    int e = blockIdx.x;
    int tid = threadIdx.x;
    int lane = tid & 31, wid = tid >> 5;
    __shared__ int wsum[8];
    __shared__ int base_s;
    if (tid == 0) base_s = 0;
    __syncthreads();
    for (int t0 = 0; t0 < TT; t0 += 256) {
        int t = t0 + tid;
        bool sel = false; float p = 0.f;
        if (g_e0[t] == e)      { sel = true; p = g_p0[t]; }
        else if (g_e1[t] == e) { sel = true; p = g_p1[t]; }
        unsigned m = __ballot_sync(0xffffffffu, sel);
        int rank = __popc(m & ((1u << lane) - 1));
        if (lane == 0) wsum[wid] = __popc(m);
        __syncthreads();
        int woff = 0;
        #pragma unroll
        for (int w = 0; w < 8; w++) if (w < wid) woff += wsum[w];
        if (sel) {
            int idx = base_s + woff + rank;
            g_ltok[e * TT + idx] = t;
            g_lp[e * TT + idx]   = p;
        }
        __syncthreads();
        if (tid == 0) {
            int tot = 0;
            #pragma unroll
            for (int w = 0; w < 8; w++) tot += wsum[w];
            base_s += tot;
        }
        __syncthreads();
    }
    if (tid == 0) g_cnt[e] = base_s;
}

__global__ void offsets_kernel() {
    int o = 0;
    for (int e = 0; e < EE; e++) { g_off[e] = o; o += g_cnt[e]; }
}

// ---------------- generic 128x128x16 fp32 SGEMM (8x8 per-thread tiles) ----------------
// MODE 0: C=g_sg   = x @ shared_gate_w                 (A=x,   K=DD, N=II)
// MODE 1: C=g_sh   = silu(g_sg) * (x @ shared_up_w)    (A=x,   K=DD, N=II)
// MODE 2: C=out    = g_sh @ shared_down_w              (A=g_sh,K=II, N=DD)  plain store
// MODE 3: C=g_gu   = (p*x[tok]) @ gate_up_w[e]         (A=x via list, K=DD, N=2I)
// MODE 4: out[tok] += g_rh @ down_w[e]  (atomicAdd)    (A=g_rh+off,   K=II, N=DD)
template <int MODE, int KDIM, int NDIM>
__global__ void __launch_bounds__(256)
sgemm_k(const float* __restrict__ Ain, const float* __restrict__ B, float* __restrict__ outp) {
    __shared__ __align__(16) float As[16][128];
    __shared__ __align__(16) float Bs[16][128];

    const int tid = threadIdx.x;
    const int bn = blockIdx.x, bm = blockIdx.y;
    const int e = (MODE >= 3) ? blockIdx.z : 0;

    int M;
    const int* ltok = nullptr;
    const float* lp = nullptr;
    const float* Ap;
    const float* Bp = B;

    if (MODE == 3) {
        M = g_cnt[e];
        if (bm * 128 >= M) return;
        ltok = g_ltok + e * TT;
        lp   = g_lp + e * TT;
        Ap = Ain;
        Bp = B + (size_t)e * DD * (2 * II);
    } else if (MODE == 4) {
        M = g_cnt[e];
        if (bm * 128 >= M) return;
        ltok = g_ltok + e * TT;
        Ap = g_rh + (size_t)g_off[e] * II;
        Bp = B + (size_t)e * II * DD;
    } else if (MODE == 2) {
        M = TT; Ap = g_sh;
    } else {
        M = TT; Ap = Ain;
    }

    const int row0 = bm * 128, col0 = bn * 128;
    const int tx = tid & 15, ty = tid >> 4;

    float acc[8][8];
    #pragma unroll
    for (int i = 0; i < 8; i++)
        #pragma unroll
        for (int j = 0; j < 8; j++) acc[i][j] = 0.f;

    for (int k0 = 0; k0 < KDIM; k0 += 16) {
        // A tile 128x16 -> As[k][m]
        #pragma unroll
        for (int i = 0; i < 2; i++) {
            int f = tid + i * 256;
            int r = f >> 2;
            int c = (f & 3) * 4;
            float4 v = make_float4(0.f, 0.f, 0.f, 0.f);
            int gr = row0 + r;
            if (gr < M) {
                if (MODE == 3) {
                    int tok = ltok[gr];
                    float p = lp[gr];
                    v = *(const float4*)(Ap + (size_t)tok * KDIM + k0 + c);
                    v.x *= p; v.y *= p; v.z *= p; v.w *= p;
                } else {
                    v = *(const float4*)(Ap + (size_t)gr * KDIM + k0 + c);
                }
            }
            As[c    ][r] = v.x;
            As[c + 1][r] = v.y;
            As[c + 2][r] = v.z;
            As[c + 3][r] = v.w;
        }
        // B tile 16x128 -> Bs[k][n]
        #pragma unroll
        for (int i = 0; i < 2; i++) {
            int f = tid + i * 256;
            int r = f >> 5;
            int c = (f & 31) * 4;
            *(float4*)(&Bs[r][c]) = *(const float4*)(Bp + (size_t)(k0 + r) * NDIM + col0 + c);
        }
        __syncthreads();

        #pragma unroll
        for (int kk = 0; kk < 16; kk++) {
            float4 a0 = *(const float4*)(&As[kk][ty * 8]);
            float4 a1 = *(const float4*)(&As[kk][ty * 8 + 4]);
            float4 b0 = *(const float4*)(&Bs[kk][tx * 8]);
            float4 b1 = *(const float4*)(&Bs[kk][tx * 8 + 4]);
            float a[8] = {a0.x, a0.y, a0.z, a0.w, a1.x, a1.y, a1.z, a1.w};
            float b[8] = {b0.x, b0.y, b0.z, b0.w, b1.x, b1.y, b1.z, b1.w};
            #pragma unroll
            for (int i = 0; i < 8; i++)
                #pragma unroll
                for (int j = 0; j < 8; j++)
                    acc[i][j] = fmaf(a[i], b[j], acc[i][j]);
        }
        __syncthreads();
    }

    // ---------------- epilogue ----------------
    const int row_t = row0 + ty * 8;
    const int col_t = col0 + tx * 8;

    if (MODE == 4) {
        #pragma unroll
        for (int i = 0; i < 8; i++) {
            int gr = row_t + i;
            if (gr < M) {
                int tok = ltok[gr];
                float* orow = outp + (size_t)tok * NDIM + col_t;
                #pragma unroll
                for (int j = 0; j < 8; j++) atomicAdd(orow + j, acc[i][j]);
            }
        }
        return;
    }

    float* Cb;
    if (MODE == 0)      Cb = g_sg;
    else if (MODE == 1) Cb = g_sh;
    else if (MODE == 2) Cb = outp;
    else                Cb = g_gu + (size_t)g_off[e] * (2 * II);   // MODE 3

    #pragma unroll
    for (int i = 0; i < 8; i++) {
        int gr = row_t + i;
        if (gr < M) {
            float* crow = Cb + (size_t)gr * NDIM + col_t;
            if (MODE == 1) {
                const float* grow = g_sg + (size_t)gr * NDIM + col_t;
                float4 ga = *(const float4*)(grow);
                float4 gb = *(const float4*)(grow + 4);
                float4 o0, o1;
                o0.x = siluf(ga.x) * acc[i][0]; o0.y = siluf(ga.y) * acc[i][1];
                o0.z = siluf(ga.z) * acc[i][2]; o0.w = siluf(ga.w) * acc[i][3];
                o1.x = siluf(gb.x) * acc[i][4]; o1.y = siluf(gb.y) * acc[i][5];
                o1.z = siluf(gb.z) * acc[i][6]; o1.w = siluf(gb.w) * acc[i][7];
                *(float4*)(crow)     = o0;
                *(float4*)(crow + 4) = o1;
            } else {
                float4 o0 = make_float4(acc[i][0], acc[i][1], acc[i][2], acc[i][3]);
                float4 o1 = make_float4(acc[i][4], acc[i][5], acc[i][6], acc[i][7]);
                *(float4*)(crow)     = o0;
                *(float4*)(crow + 4) = o1;
            }
        }
    }
}

// ---------------- routed activation: h = silu(gate) * up ----------------
__global__ void routed_act_kernel() {
    int idx = blockIdx.x * blockDim.x + threadIdx.x;
    const int total = RTOT * (II / 4);
    if (idx >= total) return;
    int r = idx / (II / 4);
    int c = (idx % (II / 4)) * 4;
    float4 g = *(const float4*)(g_gu + (size_t)r * (2 * II) + c);
    float4 u = *(const float4*)(g_gu + (size_t)r * (2 * II) + II + c);
    float4 h;
    h.x = siluf(g.x) * u.x; h.y = siluf(g.y) * u.y;
    h.z = siluf(g.z) * u.z; h.w = siluf(g.w) * u.w;
    *(float4*)(g_rh + (size_t)r * II + c) = h;
}

// ---------------- launch ----------------
extern "C" void kernel_launch(void* const* d_in, const int* in_sizes, int n_in,
                              void* d_out, int out_size) {
    const float* x   = (const float*)d_in[0];   // [T, D]
    const float* rw  = (const float*)d_in[1];   // [D, E]
    const float* guw = (const float*)d_in[2];   // [E, D, 2I]
    const float* dw  = (const float*)d_in[3];   // [E, I, D]
    const float* sgw = (const float*)d_in[4];   // [D, I]
    const float* suw = (const float*)d_in[5];   // [D, I]
    const float* sdw = (const float*)d_in[6];   // [I, D]
    float* out = (float*)d_out;                 // [T, D]

    router_kernel<<<TT / 8, 256>>>(x, rw);
    build_lists_kernel<<<EE, 256>>>();
    offsets_kernel<<<1, 1>>>();

    // shared expert
    sgemm_k<0, DD, II><<<dim3(II / 128, TT / 128), 256>>>(x, sgw, nullptr);
    sgemm_k<1, DD, II><<<dim3(II / 128, TT / 128), 256>>>(x, suw, nullptr);
    sgemm_k<2, II, DD><<<dim3(DD / 128, TT / 128), 256>>>(nullptr, sdw, out);

    // routed experts (sparse grouped)
    sgemm_k<3, DD, 2 * II><<<dim3((2 * II) / 128, TT / 128, EE), 256>>>(x, guw, nullptr);
    routed_act_kernel<<<(RTOT * (II / 4) + 255) / 256, 256>>>();
    sgemm_k<4, II, DD><<<dim3(DD / 128, TT / 128, EE), 256>>>(nullptr, dw, out);
}

// round 5
// speedup vs baseline: 2.5829x; 2.5829x over previous
#include <cuda_runtime.h>
#include <cuda_bf16.h>
#include <cstdint>
#include <math.h>

// ---------------- problem constants ----------------
#define TT 4096
#define DDIM 2048
#define IDIM 1024
#define EE 8
#define RTOT (2*TT)
#define GTOT (RTOT+TT)

// ---------------- GEMM tiling ----------------
#define KT 32
#define ROW_B 80                 // padded row: 32 bf16 (64B) + 16B pad; 20 words -> conflict-free
#define ARR_B (128 * ROW_B)      // 10240 bytes per operand array
#define STAGE_B (4 * ARR_B)      // Ahi|Alo|Bhi|Blo = 40960
#define SMEM_BYTES (2 * STAGE_B) // 81920

// ---------------- scratch ----------------
__device__ unsigned short g_xhi[(size_t)TT * DDIM];
__device__ unsigned short g_xlo[(size_t)TT * DDIM];
__device__ unsigned short g_bguh[(size_t)9 * 2048 * 2048];  // gate_up^T [e][n][k] hi
__device__ unsigned short g_bgul[(size_t)9 * 2048 * 2048];
__device__ unsigned short g_bdnh[(size_t)9 * 2048 * 1024];  // down^T [e][n][k] hi
__device__ unsigned short g_bdnl[(size_t)9 * 2048 * 1024];
__device__ float g_gu[(size_t)GTOT * 2048];
__device__ unsigned short g_rhh[(size_t)GTOT * 1024];
__device__ unsigned short g_rhl[(size_t)GTOT * 1024];
__device__ int   g_e0[TT], g_e1[TT];
__device__ float g_p0[TT], g_p1[TT];
__device__ int   g_cnt[EE];
__device__ int   g_off[EE];
__device__ int   g_ltok[EE * TT];
__device__ float g_lp[EE * TT];

__device__ __forceinline__ float siluf(float v) { return v / (1.0f + __expf(-v)); }

__device__ __forceinline__ void splitbf(float v, unsigned short& h, unsigned short& l) {
    __nv_bfloat16 bh = __float2bfloat16(v);
    float rem = v - __bfloat162float(bh);
    __nv_bfloat16 bl = __float2bfloat16(rem);
    h = __bfloat16_as_ushort(bh);
    l = __bfloat16_as_ushort(bl);
}

__device__ __forceinline__ uint32_t smem_u32(const void* p) {
    uint32_t a;
    asm("{ .reg .u64 t; cvta.to.shared.u64 t, %1; cvt.u32.u64 %0, t; }" : "=r"(a) : "l"(p));
    return a;
}

#define CP16(dst, src) \
    asm volatile("cp.async.cg.shared.global [%0], [%1], 16;" :: "r"(dst), "l"(src) : "memory")
#define CP_COMMIT() asm volatile("cp.async.commit_group;" ::: "memory")
#define CP_WAIT(n)  asm volatile("cp.async.wait_group %0;" :: "n"(n) : "memory")

__device__ __forceinline__ void mma16(float* c, const uint32_t* a, const uint32_t* b) {
    asm volatile(
        "mma.sync.aligned.m16n8k16.row.col.f32.bf16.bf16.f32 "
        "{%0,%1,%2,%3}, {%4,%5,%6,%7}, {%8,%9}, {%0,%1,%2,%3};"
        : "+f"(c[0]), "+f"(c[1]), "+f"(c[2]), "+f"(c[3])
        : "r"(a[0]), "r"(a[1]), "r"(a[2]), "r"(a[3]), "r"(b[0]), "r"(b[1]));
}

// ---------------- conversion passes ----------------
__global__ void split_x_kernel(const float* __restrict__ x) {
    size_t i = ((size_t)blockIdx.x * blockDim.x + threadIdx.x) * 4;
    float4 v = *(const float4*)(x + i);
    ushort4 h, l;
    splitbf(v.x, h.x, l.x); splitbf(v.y, h.y, l.y);
    splitbf(v.z, h.z, l.z); splitbf(v.w, h.w, l.w);
    *(ushort4*)(g_xhi + i) = h;
    *(ushort4*)(g_xlo + i) = l;
}

// gate_up^T: W[k][n] (e<8: guw, ld=2048; e==8: sgw|suw concat, ld=1024) -> [e][n][2048]
__global__ void transsplit_gu(const float* __restrict__ guw,
                              const float* __restrict__ sgw,
                              const float* __restrict__ suw) {
    __shared__ float tile[32][33];
    int e = blockIdx.z;
    int n0 = blockIdx.x * 32, k0 = blockIdx.y * 32;
    const float* src; int ld, nsrc0;
    if (e < 8) { src = guw + (size_t)e * 2048 * 2048; ld = 2048; nsrc0 = n0; }
    else if (n0 < 1024) { src = sgw; ld = 1024; nsrc0 = n0; }
    else { src = suw; ld = 1024; nsrc0 = n0 - 1024; }
    #pragma unroll
    for (int j = 0; j < 4; j++) {
        int k = k0 + threadIdx.y + j * 8;
        tile[threadIdx.y + j * 8][threadIdx.x] = src[(size_t)k * ld + nsrc0 + threadIdx.x];
    }
    __syncthreads();
    #pragma unroll
    for (int j = 0; j < 4; j++) {
        int n = n0 + threadIdx.y + j * 8;
        float v = tile[threadIdx.x][threadIdx.y + j * 8];
        unsigned short h, l;
        splitbf(v, h, l);
        size_t di = ((size_t)e * 2048 + n) * 2048 + k0 + threadIdx.x;
        g_bguh[di] = h; g_bgul[di] = l;
    }
}

// down^T: W[k=1024][n=2048] -> [e][n][1024]
__global__ void transsplit_dn(const float* __restrict__ dw, const float* __restrict__ sdw) {
    __shared__ float tile[32][33];
    int e = blockIdx.z;
    int n0 = blockIdx.x * 32, k0 = blockIdx.y * 32;
    const float* src = (e < 8) ? (dw + (size_t)e * 1024 * 2048) : sdw;
    #pragma unroll
    for (int j = 0; j < 4; j++) {
        int k = k0 + threadIdx.y + j * 8;
        tile[threadIdx.y + j * 8][threadIdx.x] = src[(size_t)k * 2048 + n0 + threadIdx.x];
    }
    __syncthreads();
    #pragma unroll
    for (int j = 0; j < 4; j++) {
        int n = n0 + threadIdx.y + j * 8;
        float v = tile[threadIdx.x][threadIdx.y + j * 8];
        unsigned short h, l;
        splitbf(v, h, l);
        size_t di = ((size_t)e * 2048 + n) * 1024 + k0 + threadIdx.x;
        g_bdnh[di] = h; g_bdnl[di] = l;
    }
}

// ---------------- router ----------------
__global__ void router_kernel(const float* __restrict__ x, const float* __restrict__ rw) {
    int gwarp = (blockIdx.x * blockDim.x + threadIdx.x) >> 5;
    int lane = threadIdx.x & 31;
    if (gwarp >= TT) return;
    const float* xr = x + (size_t)gwarp * DDIM;
    float acc[8] = {0.f,0.f,0.f,0.f,0.f,0.f,0.f,0.f};
    for (int d = lane; d < DDIM; d += 32) {
        float xv = xr[d];
        const float4* r4 = (const float4*)(rw + (size_t)d * EE);
        float4 a = r4[0], b = r4[1];
        acc[0] += xv * a.x; acc[1] += xv * a.y; acc[2] += xv * a.z; acc[3] += xv * a.w;
        acc[4] += xv * b.x; acc[5] += xv * b.y; acc[6] += xv * b.z; acc[7] += xv * b.w;
    }
    #pragma unroll
    for (int e = 0; e < 8; e++)
        #pragma unroll
        for (int s = 16; s > 0; s >>= 1)
            acc[e] += __shfl_xor_sync(0xffffffffu, acc[e], s);
    if (lane == 0) {
        int i0 = 0; float v0 = acc[0];
        #pragma unroll
        for (int e = 1; e < 8; e++) if (acc[e] > v0) { v0 = acc[e]; i0 = e; }
        int i1 = -1; float v1 = -3.4e38f;
        #pragma unroll
        for (int e = 0; e < 8; e++) if (e != i0 && acc[e] > v1) { v1 = acc[e]; i1 = e; }
        g_e0[gwarp] = i0; g_e1[gwarp] = i1;
        g_p0[gwarp] = 1.0f / (1.0f + __expf(-v0));
        g_p1[gwarp] = 1.0f / (1.0f + __expf(-v1));
    }
}

__global__ void build_lists_kernel() {
    int e = blockIdx.x;
    int tid = threadIdx.x;
    int lane = tid & 31, wid = tid >> 5;
    __shared__ int wsum[8];
    __shared__ int base_s;
    if (tid == 0) base_s = 0;
    __syncthreads();
    for (int t0 = 0; t0 < TT; t0 += 256) {
        int t = t0 + tid;
        bool sel = false; float p = 0.f;
        if (g_e0[t] == e)      { sel = true; p = g_p0[t]; }
        else if (g_e1[t] == e) { sel = true; p = g_p1[t]; }
        unsigned m = __ballot_sync(0xffffffffu, sel);
        int rank = __popc(m & ((1u << lane) - 1));
        if (lane == 0) wsum[wid] = __popc(m);
        __syncthreads();
        int woff = 0;
        #pragma unroll
        for (int w = 0; w < 8; w++) if (w < wid) woff += wsum[w];
        if (sel) {
            int idx = base_s + woff + rank;
            g_ltok[e * TT + idx] = t;
            g_lp[e * TT + idx]   = p;
        }
        __syncthreads();
        if (tid == 0) {
            int tot = 0;
            #pragma unroll
            for (int w = 0; w < 8; w++) tot += wsum[w];
            base_s += tot;
        }
        __syncthreads();
    }
    if (tid == 0) g_cnt[e] = base_s;
}

__global__ void offsets_kernel() {
    int o = 0;
    for (int e = 0; e < EE; e++) { g_off[e] = o; o += g_cnt[e]; }
}

// ---------------- split-bf16 3-MMA grouped GEMM ----------------
// MODE 0: gate_up  g_gu[slot] = p*(x[tok] @ Wgu[e]),  K=2048, z=e (0..8; 8=shared,p=1)
// MODE 1: shared down: out[row] = rh[RTOT+row] @ Wdn[8]  plain store, K=1024
// MODE 2: routed down: out[tok] += rh[off+row] @ Wdn[e]  atomicAdd,  K=1024
template <int MODE>
__global__ void __launch_bounds__(256, 2)
tc_gemm(float* __restrict__ out)
{
    const int KD = (MODE == 0) ? 2048 : 1024;
    extern __shared__ char smem[];
    const uint32_t sb = smem_u32(smem);
    const int tid = threadIdx.x;
    const int e = (MODE == 1) ? 8 : blockIdx.z;
    const int row0 = blockIdx.y * 128;
    const int col0 = blockIdx.x * 128;

    int M, soff;
    const int* ltok = nullptr;
    const float* lpp = nullptr;
    if (MODE == 0) {
        if (e < 8) { M = g_cnt[e]; soff = g_off[e]; ltok = g_ltok + e * TT; lpp = g_lp + e * TT; }
        else       { M = TT; soff = RTOT; }
    } else if (MODE == 1) { M = TT; soff = RTOT; }
    else { M = g_cnt[e]; soff = g_off[e]; ltok = g_ltok + e * TT; }
    if (row0 >= M) return;

    const unsigned short* Bh = ((MODE == 0) ? g_bguh : g_bdnh) + ((size_t)e * 2048 + col0) * KD;
    const unsigned short* Bl = ((MODE == 0) ? g_bgul : g_bdnl) + ((size_t)e * 2048 + col0) * KD;

    // per-thread cp.async plan: 8 chunks of 16B (Ahi, Alo, Bhi, Blo; 512 chunks each)
    const char* src[8]; uint32_t dst[8];
    #pragma unroll
    for (int i = 0; i < 8; i++) {
        int idx = tid + i * 256;
        int arr = idx >> 9;
        int ci = idx & 511;
        int r = ci >> 2, ch = ci & 3;
        const unsigned short* rowp;
        if (arr <= 1) {          // A side
            int gr = row0 + r;
            if (MODE == 0) {
                size_t tok;
                if (e < 8) tok = (gr < M) ? (size_t)ltok[gr] : 0;
                else       tok = (size_t)gr;
                rowp = ((arr == 0) ? g_xhi : g_xlo) + tok * DDIM;
            } else {
                size_t slot = (MODE == 1) ? (size_t)(RTOT + gr)
                                          : (size_t)(soff + ((gr < M) ? gr : 0));
                rowp = ((arr == 0) ? g_rhh : g_rhl) + slot * IDIM;
            }
        } else {                 // B side
            rowp = ((arr == 2) ? Bh : Bl) + (size_t)r * KD;
        }
        src[i] = (const char*)rowp + ch * 16;
        dst[i] = sb + (uint32_t)(arr * ARR_B + r * ROW_B + ch * 16);
    }

    const int lane = tid & 31;
    const int g = lane >> 2, t = lane & 3;
    const int wm = (tid >> 5) & 1, wn = (tid >> 5) >> 1;

    float acc[4][4][4];
    #pragma unroll
    for (int mi = 0; mi < 4; mi++)
        #pragma unroll
        for (int ni = 0; ni < 4; ni++)
            #pragma unroll
            for (int r = 0; r < 4; r++) acc[mi][ni][r] = 0.f;

    // prefetch tile 0 -> stage 0
    #pragma unroll
    for (int i = 0; i < 8; i++) { CP16(dst[i], src[i]); src[i] += 64; }
    CP_COMMIT();

    const int NK = KD / KT;
    for (int it = 0; it < NK; it++) {
        if (it + 1 < NK) {
            uint32_t so = (uint32_t)(((it + 1) & 1) * STAGE_B);
            #pragma unroll
            for (int i = 0; i < 8; i++) { CP16(dst[i] + so, src[i]); src[i] += 64; }
            CP_COMMIT();
            CP_WAIT(1);
        } else {
            CP_WAIT(0);
        }
        __syncthreads();

        const uint32_t* Sa = (const uint32_t*)(smem + (size_t)(it & 1) * STAGE_B);
        const uint32_t* SAh = Sa;
        const uint32_t* SAl = Sa + ARR_B / 4;
        const uint32_t* SBh = Sa + 2 * (ARR_B / 4);
        const uint32_t* SBl = Sa + 3 * (ARR_B / 4);

        #pragma unroll
        for (int s = 0; s < 2; s++) {        // two k16 steps
            const int kb = s * 8 + t;
            uint32_t bh[4][2], bl[4][2];
            #pragma unroll
            for (int ni = 0; ni < 4; ni++) {
                int cb = wn * 32 + ni * 8 + g;
                int i0 = cb * 20 + kb;
                bh[ni][0] = SBh[i0]; bh[ni][1] = SBh[i0 + 4];
                bl[ni][0] = SBl[i0]; bl[ni][1] = SBl[i0 + 4];
            }
            #pragma unroll
            for (int mi = 0; mi < 4; mi++) {
                int rb = wm * 64 + mi * 16 + g;
                int i0 = rb * 20 + kb;
                int i8 = (rb + 8) * 20 + kb;
                uint32_t ah[4] = { SAh[i0], SAh[i8], SAh[i0 + 4], SAh[i8 + 4] };
                uint32_t al[4] = { SAl[i0], SAl[i8], SAl[i0 + 4], SAl[i8 + 4] };
                #pragma unroll
                for (int ni = 0; ni < 4; ni++) {
                    mma16(acc[mi][ni], ah, bh[ni]);
                    mma16(acc[mi][ni], ah, bl[ni]);
                    mma16(acc[mi][ni], al, bh[ni]);
                }
            }
        }
        __syncthreads();
    }

    // ---------------- epilogue ----------------
    #pragma unroll
    for (int mi = 0; mi < 4; mi++) {
        int gr0 = row0 + wm * 64 + mi * 16 + g;
        int gr1 = gr0 + 8;
        bool v0 = gr0 < M, v1 = gr1 < M;

        if (MODE == 0) {
            float p0 = 1.f, p1 = 1.f;
            if (e < 8) { p0 = v0 ? lpp[gr0] : 0.f; p1 = v1 ? lpp[gr1] : 0.f; }
            float* d0 = g_gu + (size_t)(soff + gr0) * 2048 + col0 + wn * 32;
            float* d1 = g_gu + (size_t)(soff + gr1) * 2048 + col0 + wn * 32;
            #pragma unroll
            for (int ni = 0; ni < 4; ni++) {
                int cc = ni * 8 + 2 * t;
                if (v0) { float2 v; v.x = p0 * acc[mi][ni][0]; v.y = p0 * acc[mi][ni][1]; *(float2*)(d0 + cc) = v; }
                if (v1) { float2 v; v.x = p1 * acc[mi][ni][2]; v.y = p1 * acc[mi][ni][3]; *(float2*)(d1 + cc) = v; }
            }
        } else if (MODE == 1) {
            float* d0 = out + (size_t)gr0 * 2048 + col0 + wn * 32;
            float* d1 = out + (size_t)gr1 * 2048 + col0 + wn * 32;
            #pragma unroll
            for (int ni = 0; ni < 4; ni++) {
                int cc = ni * 8 + 2 * t;
                float2 v;
                v.x = acc[mi][ni][0]; v.y = acc[mi][ni][1]; *(float2*)(d0 + cc) = v;
                v.x = acc[mi][ni][2]; v.y = acc[mi][ni][3]; *(float2*)(d1 + cc) = v;
            }
        } else {
            int tok0 = v0 ? ltok[gr0] : 0;
            int tok1 = v1 ? ltok[gr1] : 0;
            float* d0 = out + (size_t)tok0 * 2048 + col0 + wn * 32;
            float* d1 = out + (size_t)tok1 * 2048 + col0 + wn * 32;
            #pragma unroll
            for (int ni = 0; ni < 4; ni++) {
                int cc = ni * 8 + 2 * t;
                if (v0) { atomicAdd(d0 + cc, acc[mi][ni][0]); atomicAdd(d0 + cc + 1, acc[mi][ni][1]); }
                if (v1) { atomicAdd(d1 + cc, acc[mi][ni][2]); atomicAdd(d1 + cc + 1, acc[mi][ni][3]); }
            }
        }
    }
}

// ---------------- activation: h = silu(gate)*up, split to bf16 hi/lo ----------------
__global__ void act_kernel() {
    int r = blockIdx.x;
    int c = threadIdx.x * 4;
    float4 gv = *(const float4*)(g_gu + (size_t)r * 2048 + c);
    float4 uv = *(const float4*)(g_gu + (size_t)r * 2048 + 1024 + c);
    float4 h;
    h.x = siluf(gv.x) * uv.x; h.y = siluf(gv.y) * uv.y;
    h.z = siluf(gv.z) * uv.z; h.w = siluf(gv.w) * uv.w;
    ushort4 hh, hl;
    splitbf(h.x, hh.x, hl.x); splitbf(h.y, hh.y, hl.y);
    splitbf(h.z, hh.z, hl.z); splitbf(h.w, hh.w, hl.w);
    *(ushort4*)(g_rhh + (size_t)r * 1024 + c) = hh;
    *(ushort4*)(g_rhl + (size_t)r * 1024 + c) = hl;
}

// ---------------- launch ----------------
extern "C" void kernel_launch(void* const* d_in, const int* in_sizes, int n_in,
                              void* d_out, int out_size) {
    const float* x   = (const float*)d_in[0];
    const float* rw  = (const float*)d_in[1];
    const float* guw = (const float*)d_in[2];
    const float* dw  = (const float*)d_in[3];
    const float* sgw = (const float*)d_in[4];
    const float* suw = (const float*)d_in[5];
    const float* sdw = (const float*)d_in[6];
    float* out = (float*)d_out;

    cudaFuncSetAttribute(tc_gemm<0>, cudaFuncAttributeMaxDynamicSharedMemorySize, SMEM_BYTES);
    cudaFuncSetAttribute(tc_gemm<1>, cudaFuncAttributeMaxDynamicSharedMemorySize, SMEM_BYTES);
    cudaFuncSetAttribute(tc_gemm<2>, cudaFuncAttributeMaxDynamicSharedMemorySize, SMEM_BYTES);

    // conversions (independent of router)
    split_x_kernel<<<(TT * DDIM) / 1024, 256>>>(x);
    transsplit_gu<<<dim3(64, 64, 9), dim3(32, 8)>>>(guw, sgw, suw);
    transsplit_dn<<<dim3(64, 32, 9), dim3(32, 8)>>>(dw, sdw);

    router_kernel<<<TT / 8, 256>>>(x, rw);
    build_lists_kernel<<<EE, 256>>>();
    offsets_kernel<<<1, 1>>>();

    tc_gemm<0><<<dim3(16, 32, 9), 256, SMEM_BYTES>>>(nullptr);
    act_kernel<<<GTOT, 256>>>();
    tc_gemm<1><<<dim3(16, 32, 1), 256, SMEM_BYTES>>>(out);
    tc_gemm<2><<<dim3(16, 32, 8), 256, SMEM_BYTES>>>(out);
}